// round 10
// baseline (speedup 1.0000x reference)
#include <cuda_runtime.h>
#include <cuda_fp16.h>
#include <cstdint>

// Masked LeNet-C3 conv via fp16 mma.sync.m16n8k16 (HMMA) implicit GEMM on sm_103.
// x: [64,6,512,512] f32, W: [16,6,5,5] f32, b: [16] f32 -> out: [64,16,508,508] f32
//
// Round 10: same algorithm/layout as round 9 (proven correct, rel_err 2.9e-4), but all
// accumulators and MMA operands are named scalar registers (no arrays near inline asm)
// to kill the local-memory demotion that produced L1=90%/L2=71%/issue=14%.

#define NIC 6
#define NOC 16
#define IH 512
#define IW 512
#define OH 508
#define OW 508
#define TILE_W 64
#define TILE_H 8
#define IN_ROWS 12
#define LCOLS 68                          // loaded cols 0..67 (64 + 4 halo)
#define BLK_ROW 40                        // 8B blocks per row (cols 0..79; >67 stay zero)
#define COPY_BLKS (3 * IN_ROWS * BLK_ROW) // 1440
#define COPY_STRIDE (COPY_BLKS + 8)       // +8 blocks => +16 banks between copies
#define NSTEP 15
#define NTHREADS 256

typedef unsigned long long ull;

__host__ __device__ constexpr float conn(int ic, int oc) {
    constexpr int M[NIC][NOC] = {
        {1,0,0,0,1,1,1,0,0,1,1,1,1,0,1,1},
        {1,1,0,0,0,1,1,1,0,0,1,1,1,1,0,1},
        {1,1,1,0,0,0,1,1,1,0,0,1,0,1,1,1},
        {0,1,1,1,0,0,1,1,1,1,0,0,1,0,1,1},
        {0,0,1,1,1,0,0,1,1,1,1,0,1,1,0,1},
        {0,0,0,1,1,1,0,0,1,1,1,1,0,1,1,1},
    };
    return (float)M[ic][oc];
}

__device__ __forceinline__ uint32_t pack_f16x2(float lo, float hi) {
    uint32_t r;
    asm("cvt.rn.f16x2.f32 %0, %1, %2;" : "=r"(r) : "f"(hi), "f"(lo));
    return r;
}

// D(16x8,f32) += A(16x16,f16) * B(16x8,f16) — all operands scalar refs/values.
__device__ __forceinline__ void mma_f16(float& d0, float& d1, float& d2, float& d3,
                                        uint32_t a0, uint32_t a1, uint32_t a2, uint32_t a3,
                                        uint32_t b0, uint32_t b1) {
    asm("mma.sync.aligned.m16n8k16.row.col.f32.f16.f16.f32 "
        "{%0,%1,%2,%3}, {%4,%5,%6,%7}, {%8,%9}, {%0,%1,%2,%3};"
        : "+f"(d0), "+f"(d1), "+f"(d2), "+f"(d3)
        : "r"(a0), "r"(a1), "r"(a2), "r"(a3), "r"(b0), "r"(b1));
}

__global__ __launch_bounds__(NTHREADS, 3)
void conv_c3_hmma(const float* __restrict__ x,
                  const float* __restrict__ W,
                  const float* __restrict__ b,
                  float* __restrict__ out)
{
    __shared__ __align__(16) ull      s_in[2 * COPY_STRIDE];      // 23168 B
    __shared__ __align__(16) uint32_t s_B[NSTEP * NOC * 8];       //  7680 B
    __shared__ float s_b[NOC];

    const int tid  = threadIdx.x;
    const int lane = tid & 31;
    const int warp = tid >> 5;
    const int n    = blockIdx.z;
    const int by0  = blockIdx.y * TILE_H;
    const int bx0  = blockIdx.x * TILE_W;

    // ---- Zero-init interleaved region ----
    #pragma unroll 1
    for (int i = tid; i < 2 * COPY_STRIDE; i += NTHREADS) s_in[i] = 0ull;

    // ---- Weight table: step s=(ky*3+icp); per oc 8 u32: [j][half=ic_local] ----
    #pragma unroll 1
    for (int idx = tid; idx < NSTEP * NOC * 8; idx += NTHREADS) {
        int half = idx & 1;
        int j    = (idx >> 1) & 3;
        int oc   = (idx >> 3) & 15;
        int s    = idx >> 7;
        int ky   = s / 3;
        int ic   = 2 * (s % 3) + half;
        int kx0  = 2 * j;
        float w0 = (kx0 < 5)     ? W[oc * (NIC*25) + ic * 25 + ky * 5 + kx0]     * conn(ic, oc) : 0.f;
        float w1 = (kx0 + 1 < 5) ? W[oc * (NIC*25) + ic * 25 + ky * 5 + kx0 + 1] * conn(ic, oc) : 0.f;
        s_B[idx] = pack_f16x2(w0, w1);
    }
    if (tid < NOC) s_b[tid] = b[tid];
    __syncthreads();

    // ---- Input tile: coalesced f32 LDG, fp16 convert, scatter STS.16 x2 ----
    const float* xin = x + (size_t)n * NIC * IH * IW;
    unsigned short* hw = (unsigned short*)s_in;
    #pragma unroll 1
    for (int idx = tid; idx < NIC * IN_ROWS * LCOLS; idx += NTHREADS) {
        int col = idx % LCOLS;
        int row = (idx / LCOLS) % IN_ROWS;
        int ic  = idx / (LCOLS * IN_ROWS);
        int gy  = by0 + row;
        int gx  = bx0 + col;
        float v = 0.f;
        if (gy < IH && gx < IW)
            v = __ldg(&xin[((size_t)ic * IH + gy) * IW + gx]);
        unsigned short hb = __half_as_ushort(__float2half_rn(v));
        int icp = ic >> 1, icl = ic & 1;
        int rowbase = icp * (IN_ROWS * BLK_ROW) + row * BLK_ROW;
        hw[(rowbase + (col >> 1)) * 4 + 2 * icl + (col & 1)] = hb;
        if (col >= 1)
            hw[(COPY_STRIDE + rowbase + ((col - 1) >> 1)) * 4 + 2 * icl + ((col - 1) & 1)] = hb;
    }
    __syncthreads();

    // ---- Main loop: named scalar accumulators, zero array indexing near asm ----
    const int g  = lane >> 2;
    const int c4 = lane & 3;
    const int p  = g & 1;
    const int wy = warp;
    const ull* abase = s_in + p * COPY_STRIDE + ((g - p) >> 1) + c4;

#define DECL_ACC(mt) \
    float ac##mt##_0_0 = 0.f, ac##mt##_0_1 = 0.f, ac##mt##_0_2 = 0.f, ac##mt##_0_3 = 0.f, \
          ac##mt##_1_0 = 0.f, ac##mt##_1_1 = 0.f, ac##mt##_1_2 = 0.f, ac##mt##_1_3 = 0.f;
    DECL_ACC(0) DECL_ACC(1) DECL_ACC(2) DECL_ACC(3)

#define MMA_MT(mt) { \
    ull xw0 = ap[8 * mt]; \
    ull xw1 = ap[8 * mt + 4]; \
    uint32_t A0 = (uint32_t)xw0, A1 = (uint32_t)xw1; \
    uint32_t A2 = (uint32_t)(xw0 >> 32), A3 = (uint32_t)(xw1 >> 32); \
    mma_f16(ac##mt##_0_0, ac##mt##_0_1, ac##mt##_0_2, ac##mt##_0_3, A0, A1, A2, A3, bL0, bL1); \
    mma_f16(ac##mt##_1_0, ac##mt##_1_1, ac##mt##_1_2, ac##mt##_1_3, A0, A1, A2, A3, bH0, bH1); }

    #pragma unroll 1
    for (int ky = 0; ky < 5; ky++) {
        #pragma unroll
        for (int icp = 0; icp < 3; icp++) {
            const int s = ky * 3 + icp;
            ull blv = *(const ull*)(s_B + s * 128 + g * 8 + c4 * 2);
            ull bhv = *(const ull*)(s_B + s * 128 + 64 + g * 8 + c4 * 2);
            uint32_t bL0 = (uint32_t)blv, bL1 = (uint32_t)(blv >> 32);
            uint32_t bH0 = (uint32_t)bhv, bH1 = (uint32_t)(bhv >> 32);
            const ull* ap = abase + (icp * IN_ROWS + wy + ky) * BLK_ROW;
            MMA_MT(0) MMA_MT(1) MMA_MT(2) MMA_MT(3)
        }
    }

    // ---- Epilogue: D(row m=g -> pixel, col n=2*c4+half*8.. -> oc), + bias ----
    const int y = by0 + wy;
    if (y < OH) {
#define STORE_MT(mt, h) { \
        int oc0 = h * 8 + 2 * c4; \
        float bo0 = s_b[oc0], bo1 = s_b[oc0 + 1]; \
        int x0 = bx0 + mt * 16 + g; \
        size_t base0 = (((size_t)n * NOC + oc0) * OH + y) * OW; \
        size_t base1 = base0 + (size_t)OH * OW; \
        if (x0 < OW) { \
            out[base0 + x0] = ac##mt##_##h##_0 + bo0; \
            out[base1 + x0] = ac##mt##_##h##_1 + bo1; \
        } \
        if (x0 + 8 < OW) { \
            out[base0 + x0 + 8] = ac##mt##_##h##_2 + bo0; \
            out[base1 + x0 + 8] = ac##mt##_##h##_3 + bo1; \
        } }
        STORE_MT(0, 0) STORE_MT(0, 1)
        STORE_MT(1, 0) STORE_MT(1, 1)
        STORE_MT(2, 0) STORE_MT(2, 1)
        STORE_MT(3, 0) STORE_MT(3, 1)
    }
}

extern "C" void kernel_launch(void* const* d_in, const int* in_sizes, int n_in,
                              void* d_out, int out_size) {
    const float* x = (const float*)d_in[0];
    const float* W = (const float*)d_in[1];
    const float* b = (const float*)d_in[2];
    float* out = (float*)d_out;

    const int n_batch = in_sizes[0] / (NIC * IH * IW);   // 64
    dim3 grid((OW + TILE_W - 1) / TILE_W,    // 8
              (OH + TILE_H - 1) / TILE_H,    // 64
              n_batch);                       // 64
    conv_c3_hmma<<<grid, NTHREADS>>>(x, W, b, out);
}

// round 11
// speedup vs baseline: 1.0017x; 1.0017x over previous
#include <cuda_runtime.h>
#include <cuda_fp16.h>
#include <cstdint>

// Masked LeNet-C3 conv via fp16 mma.sync.m16n8k16 (HMMA) implicit GEMM on sm_103.
// x: [64,6,512,512] f32, W: [16,6,5,5] f32, b: [16] f32 -> out: [64,16,508,508] f32
//
// Round 11: identical to round 10 except __launch_bounds__(256, 2): the (256,3)
// 84-reg cap was forcing ptxas to demote accumulators to local memory
// (regs=68 + 47GB of L1/L2 LDL/STL traffic). 128-reg cap removes the spill.

#define NIC 6
#define NOC 16
#define IH 512
#define IW 512
#define OH 508
#define OW 508
#define TILE_W 64
#define TILE_H 8
#define IN_ROWS 12
#define LCOLS 68                          // loaded cols 0..67 (64 + 4 halo)
#define BLK_ROW 40                        // 8B blocks per row (cols 0..79; >67 stay zero)
#define COPY_BLKS (3 * IN_ROWS * BLK_ROW) // 1440
#define COPY_STRIDE (COPY_BLKS + 8)       // +8 blocks => +16 banks between copies
#define NSTEP 15
#define NTHREADS 256

typedef unsigned long long ull;

__host__ __device__ constexpr float conn(int ic, int oc) {
    constexpr int M[NIC][NOC] = {
        {1,0,0,0,1,1,1,0,0,1,1,1,1,0,1,1},
        {1,1,0,0,0,1,1,1,0,0,1,1,1,1,0,1},
        {1,1,1,0,0,0,1,1,1,0,0,1,0,1,1,1},
        {0,1,1,1,0,0,1,1,1,1,0,0,1,0,1,1},
        {0,0,1,1,1,0,0,1,1,1,1,0,1,1,0,1},
        {0,0,0,1,1,1,0,0,1,1,1,1,0,1,1,1},
    };
    return (float)M[ic][oc];
}

__device__ __forceinline__ uint32_t pack_f16x2(float lo, float hi) {
    uint32_t r;
    asm("cvt.rn.f16x2.f32 %0, %1, %2;" : "=r"(r) : "f"(hi), "f"(lo));
    return r;
}

// D(16x8,f32) += A(16x16,f16) * B(16x8,f16) — all operands scalar refs/values.
__device__ __forceinline__ void mma_f16(float& d0, float& d1, float& d2, float& d3,
                                        uint32_t a0, uint32_t a1, uint32_t a2, uint32_t a3,
                                        uint32_t b0, uint32_t b1) {
    asm("mma.sync.aligned.m16n8k16.row.col.f32.f16.f16.f32 "
        "{%0,%1,%2,%3}, {%4,%5,%6,%7}, {%8,%9}, {%0,%1,%2,%3};"
        : "+f"(d0), "+f"(d1), "+f"(d2), "+f"(d3)
        : "r"(a0), "r"(a1), "r"(a2), "r"(a3), "r"(b0), "r"(b1));
}

__global__ __launch_bounds__(NTHREADS, 2)
void conv_c3_hmma(const float* __restrict__ x,
                  const float* __restrict__ W,
                  const float* __restrict__ b,
                  float* __restrict__ out)
{
    __shared__ __align__(16) ull      s_in[2 * COPY_STRIDE];      // 23168 B
    __shared__ __align__(16) uint32_t s_B[NSTEP * NOC * 8];       //  7680 B
    __shared__ float s_b[NOC];

    const int tid  = threadIdx.x;
    const int lane = tid & 31;
    const int warp = tid >> 5;
    const int n    = blockIdx.z;
    const int by0  = blockIdx.y * TILE_H;
    const int bx0  = blockIdx.x * TILE_W;

    // ---- Zero-init interleaved region ----
    #pragma unroll 1
    for (int i = tid; i < 2 * COPY_STRIDE; i += NTHREADS) s_in[i] = 0ull;

    // ---- Weight table: step s=(ky*3+icp); per oc 8 u32: [j][half=ic_local] ----
    #pragma unroll 1
    for (int idx = tid; idx < NSTEP * NOC * 8; idx += NTHREADS) {
        int half = idx & 1;
        int j    = (idx >> 1) & 3;
        int oc   = (idx >> 3) & 15;
        int s    = idx >> 7;
        int ky   = s / 3;
        int ic   = 2 * (s % 3) + half;
        int kx0  = 2 * j;
        float w0 = (kx0 < 5)     ? W[oc * (NIC*25) + ic * 25 + ky * 5 + kx0]     * conn(ic, oc) : 0.f;
        float w1 = (kx0 + 1 < 5) ? W[oc * (NIC*25) + ic * 25 + ky * 5 + kx0 + 1] * conn(ic, oc) : 0.f;
        s_B[idx] = pack_f16x2(w0, w1);
    }
    if (tid < NOC) s_b[tid] = b[tid];
    __syncthreads();

    // ---- Input tile: coalesced f32 LDG, fp16 convert, scatter STS.16 x2 ----
    const float* xin = x + (size_t)n * NIC * IH * IW;
    unsigned short* hw = (unsigned short*)s_in;
    #pragma unroll 1
    for (int idx = tid; idx < NIC * IN_ROWS * LCOLS; idx += NTHREADS) {
        int col = idx % LCOLS;
        int row = (idx / LCOLS) % IN_ROWS;
        int ic  = idx / (LCOLS * IN_ROWS);
        int gy  = by0 + row;
        int gx  = bx0 + col;
        float v = 0.f;
        if (gy < IH && gx < IW)
            v = __ldg(&xin[((size_t)ic * IH + gy) * IW + gx]);
        unsigned short hb = __half_as_ushort(__float2half_rn(v));
        int icp = ic >> 1, icl = ic & 1;
        int rowbase = icp * (IN_ROWS * BLK_ROW) + row * BLK_ROW;
        hw[(rowbase + (col >> 1)) * 4 + 2 * icl + (col & 1)] = hb;
        if (col >= 1)
            hw[(COPY_STRIDE + rowbase + ((col - 1) >> 1)) * 4 + 2 * icl + ((col - 1) & 1)] = hb;
    }
    __syncthreads();

    // ---- Main loop: named scalar accumulators ----
    const int g  = lane >> 2;
    const int c4 = lane & 3;
    const int p  = g & 1;
    const int wy = warp;
    const ull* abase = s_in + p * COPY_STRIDE + ((g - p) >> 1) + c4;

#define DECL_ACC(mt) \
    float ac##mt##_0_0 = 0.f, ac##mt##_0_1 = 0.f, ac##mt##_0_2 = 0.f, ac##mt##_0_3 = 0.f, \
          ac##mt##_1_0 = 0.f, ac##mt##_1_1 = 0.f, ac##mt##_1_2 = 0.f, ac##mt##_1_3 = 0.f;
    DECL_ACC(0) DECL_ACC(1) DECL_ACC(2) DECL_ACC(3)

#define MMA_MT(mt) { \
    ull xw0 = ap[8 * mt]; \
    ull xw1 = ap[8 * mt + 4]; \
    uint32_t A0 = (uint32_t)xw0, A1 = (uint32_t)xw1; \
    uint32_t A2 = (uint32_t)(xw0 >> 32), A3 = (uint32_t)(xw1 >> 32); \
    mma_f16(ac##mt##_0_0, ac##mt##_0_1, ac##mt##_0_2, ac##mt##_0_3, A0, A1, A2, A3, bL0, bL1); \
    mma_f16(ac##mt##_1_0, ac##mt##_1_1, ac##mt##_1_2, ac##mt##_1_3, A0, A1, A2, A3, bH0, bH1); }

    #pragma unroll 1
    for (int ky = 0; ky < 5; ky++) {
        #pragma unroll
        for (int icp = 0; icp < 3; icp++) {
            const int s = ky * 3 + icp;
            ull blv = *(const ull*)(s_B + s * 128 + g * 8 + c4 * 2);
            ull bhv = *(const ull*)(s_B + s * 128 + 64 + g * 8 + c4 * 2);
            uint32_t bL0 = (uint32_t)blv, bL1 = (uint32_t)(blv >> 32);
            uint32_t bH0 = (uint32_t)bhv, bH1 = (uint32_t)(bhv >> 32);
            const ull* ap = abase + (icp * IN_ROWS + wy + ky) * BLK_ROW;
            MMA_MT(0) MMA_MT(1) MMA_MT(2) MMA_MT(3)
        }
    }

    // ---- Epilogue: D(row m=g -> pixel, col n=2*c4+half*8.. -> oc), + bias ----
    const int y = by0 + wy;
    if (y < OH) {
#define STORE_MT(mt, h) { \
        int oc0 = h * 8 + 2 * c4; \
        float bo0 = s_b[oc0], bo1 = s_b[oc0 + 1]; \
        int x0 = bx0 + mt * 16 + g; \
        size_t base0 = (((size_t)n * NOC + oc0) * OH + y) * OW; \
        size_t base1 = base0 + (size_t)OH * OW; \
        if (x0 < OW) { \
            out[base0 + x0] = ac##mt##_##h##_0 + bo0; \
            out[base1 + x0] = ac##mt##_##h##_1 + bo1; \
        } \
        if (x0 + 8 < OW) { \
            out[base0 + x0 + 8] = ac##mt##_##h##_2 + bo0; \
            out[base1 + x0 + 8] = ac##mt##_##h##_3 + bo1; \
        } }
        STORE_MT(0, 0) STORE_MT(0, 1)
        STORE_MT(1, 0) STORE_MT(1, 1)
        STORE_MT(2, 0) STORE_MT(2, 1)
        STORE_MT(3, 0) STORE_MT(3, 1)
    }
}

extern "C" void kernel_launch(void* const* d_in, const int* in_sizes, int n_in,
                              void* d_out, int out_size) {
    const float* x = (const float*)d_in[0];
    const float* W = (const float*)d_in[1];
    const float* b = (const float*)d_in[2];
    float* out = (float*)d_out;

    const int n_batch = in_sizes[0] / (NIC * IH * IW);   // 64
    dim3 grid((OW + TILE_W - 1) / TILE_W,    // 8
              (OH + TILE_H - 1) / TILE_H,    // 64
              n_batch);                       // 64
    conv_c3_hmma<<<grid, NTHREADS>>>(x, W, b, out);
}

// round 12
// speedup vs baseline: 3.4000x; 3.3942x over previous
#include <cuda_runtime.h>
#include <cstdint>

// Masked LeNet-C3 conv via TF32 mma.sync (HMMA) implicit GEMM on sm_103.
// x: [64,6,512,512] f32, W: [16,6,5,5] f32, b: [16] f32 -> out: [64,16,508,508] f32
//
// Round 12 = Round 7 (proven 1761us, clean profile) with all asm operands as named
// scalars (no arrays through inline-asm constraints) to eliminate MOV/ALU glue that
// consumed ~57% of issue slots.

#define NIC 6
#define NOC 16
#define IH 512
#define IW 512
#define OH 508
#define OW 508
#define TILE_W 64
#define TILE_H 8
#define IN_ROWS 12
#define IN_W 72             // 64 + 4 halo + 4 zero pad
#define NTHREADS 256

__host__ __device__ constexpr float conn(int ic, int oc) {
    constexpr int M[NIC][NOC] = {
        {1,0,0,0,1,1,1,0,0,1,1,1,1,0,1,1},
        {1,1,0,0,0,1,1,1,0,0,1,1,1,1,0,1},
        {1,1,1,0,0,0,1,1,1,0,0,1,0,1,1,1},
        {0,1,1,1,0,0,1,1,1,1,0,0,1,0,1,1},
        {0,0,1,1,1,0,0,1,1,1,1,0,1,1,0,1},
        {0,0,0,1,1,1,0,0,1,1,1,1,0,1,1,1},
    };
    return (float)M[ic][oc];
}

// round-to-nearest-even f32 -> tf32 bit pattern
__device__ __forceinline__ uint32_t f32_to_tf32(float f) {
    uint32_t u = __float_as_uint(f);
    uint32_t r = u + 0xFFFu + ((u >> 13) & 1u);
    return r & 0xFFFFE000u;
}

// D(16x8) += A(16x8) * B(8x8), tf32 inputs, f32 accumulate — scalar operands only.
#define MMA_TF32(d0, d1, d2, d3, a0, a1, a2, a3, b0, b1) \
    asm("mma.sync.aligned.m16n8k8.row.col.f32.tf32.tf32.f32 " \
        "{%0,%1,%2,%3}, {%4,%5,%6,%7}, {%8,%9}, {%0,%1,%2,%3};" \
        : "+f"(d0), "+f"(d1), "+f"(d2), "+f"(d3) \
        : "r"(a0), "r"(a1), "r"(a2), "r"(a3), "r"(b0), "r"(b1))

__global__ __launch_bounds__(NTHREADS, 3)
void conv_c3_mma(const float* __restrict__ x,
                 const float* __restrict__ W,
                 const float* __restrict__ b,
                 float* __restrict__ out)
{
    __shared__ float    s_in[NIC][IN_ROWS][IN_W];        // 20736 B (tf32-rounded)
    __shared__ uint32_t s_B[NIC * 5 * NOC * 8];          // 15360 B
    __shared__ float    s_b[NOC];

    const int tid  = threadIdx.x;
    const int lane = tid & 31;
    const int warp = tid >> 5;
    const int n    = blockIdx.z;
    const int by0  = blockIdx.y * TILE_H;
    const int bx0  = blockIdx.x * TILE_W;

    // ---- Input tile -> smem (tf32-rounded); zero outside image / pad cols ----
    #pragma unroll 1
    for (int idx = tid; idx < NIC * IN_ROWS * IN_W; idx += NTHREADS) {
        int ic  = idx / (IN_ROWS * IN_W);
        int rem = idx % (IN_ROWS * IN_W);
        int r   = rem / IN_W;
        int c   = rem % IN_W;
        int gy  = by0 + r;
        int gx  = bx0 + c;
        float v = 0.0f;
        if (c < TILE_W + 4 && gy < IH && gx < IW)
            v = __ldg(&x[(((size_t)n * NIC + ic) * IH + gy) * IW + gx]);
        s_in[ic][r][c] = __uint_as_float(f32_to_tf32(v));
    }

    // ---- Masked weight table: s_B[((ic*5+ky)*16 + oc)*8 + kx], kx>=5 -> 0 ----
    #pragma unroll 1
    for (int idx = tid; idx < NIC * 5 * NOC * 8; idx += NTHREADS) {
        int kx = idx & 7;
        int oc = (idx >> 3) & 15;
        int ky = (idx >> 7) % 5;
        int ic = idx / (5 * NOC * 8);
        float wv = 0.0f;
        if (kx < 5) wv = W[oc * (NIC * 25) + ic * 25 + ky * 5 + kx] * conn(ic, oc);
        s_B[idx] = f32_to_tf32(wv);
    }
    if (tid < NOC) s_b[tid] = b[tid];
    __syncthreads();

    // ---- Main loop: 30 K-steps (ic,ky), 8 HMMA each; all scalars named ----
    const int g    = lane >> 2;          // group id 0..7
    const int c4   = lane & 3;           // thread-in-group 0..3
    const int aoff = g + c4;             // A frag base column offset
    const int boff = g * 8 + c4;         // B frag base offset (low oc half)
    const int wy   = warp;               // output row within tile

#define DECL_ACC(mt) \
    float ac##mt##_0_0 = 0.f, ac##mt##_0_1 = 0.f, ac##mt##_0_2 = 0.f, ac##mt##_0_3 = 0.f, \
          ac##mt##_1_0 = 0.f, ac##mt##_1_1 = 0.f, ac##mt##_1_2 = 0.f, ac##mt##_1_3 = 0.f;
    DECL_ACC(0) DECL_ACC(1) DECL_ACC(2) DECL_ACC(3)

#define DO_MT(mt) { \
    uint32_t A0 = __float_as_uint(rp[mt * 16 + 0]); \
    uint32_t A1 = __float_as_uint(rp[mt * 16 + 8]); \
    uint32_t A2 = __float_as_uint(rp[mt * 16 + 4]); \
    uint32_t A3 = __float_as_uint(rp[mt * 16 + 12]); \
    MMA_TF32(ac##mt##_0_0, ac##mt##_0_1, ac##mt##_0_2, ac##mt##_0_3, \
             A0, A1, A2, A3, bL0, bL1); \
    MMA_TF32(ac##mt##_1_0, ac##mt##_1_1, ac##mt##_1_2, ac##mt##_1_3, \
             A0, A1, A2, A3, bH0, bH1); }

    #pragma unroll 1
    for (int ic = 0; ic < NIC; ic++) {
        #pragma unroll
        for (int ky = 0; ky < 5; ky++) {
            const uint32_t* Bp = s_B + (ic * 5 + ky) * (NOC * 8);
            uint32_t bL0 = Bp[boff];
            uint32_t bL1 = Bp[boff + 4];
            uint32_t bH0 = Bp[64 + boff];
            uint32_t bH1 = Bp[64 + boff + 4];
            const float* rp = &s_in[ic][wy + ky][aoff];
            DO_MT(0) DO_MT(1) DO_MT(2) DO_MT(3)
        }
    }

    // ---- Epilogue: D rows -> x, D cols -> oc ----
    const int y = by0 + wy;
    if (y < OH) {
#define STORE_MT(mt, h) { \
        int oc0 = h * 8 + 2 * c4; \
        float bo0 = s_b[oc0], bo1 = s_b[oc0 + 1]; \
        int x0 = bx0 + mt * 16 + g; \
        size_t base0 = (((size_t)n * NOC + oc0) * OH + y) * OW; \
        size_t base1 = base0 + (size_t)OH * OW; \
        if (x0 < OW) { \
            out[base0 + x0] = ac##mt##_##h##_0 + bo0; \
            out[base1 + x0] = ac##mt##_##h##_1 + bo1; \
        } \
        if (x0 + 8 < OW) { \
            out[base0 + x0 + 8] = ac##mt##_##h##_2 + bo0; \
            out[base1 + x0 + 8] = ac##mt##_##h##_3 + bo1; \
        } }
        STORE_MT(0, 0) STORE_MT(0, 1)
        STORE_MT(1, 0) STORE_MT(1, 1)
        STORE_MT(2, 0) STORE_MT(2, 1)
        STORE_MT(3, 0) STORE_MT(3, 1)
    }
}

extern "C" void kernel_launch(void* const* d_in, const int* in_sizes, int n_in,
                              void* d_out, int out_size) {
    const float* x = (const float*)d_in[0];
    const float* W = (const float*)d_in[1];
    const float* b = (const float*)d_in[2];
    float* out = (float*)d_out;

    const int n_batch = in_sizes[0] / (NIC * IH * IW);   // 64
    dim3 grid((OW + TILE_W - 1) / TILE_W,    // 8
              (OH + TILE_H - 1) / TILE_H,    // 64
              n_batch);                       // 64
    conv_c3_mma<<<grid, NTHREADS>>>(x, W, b, out);
}